// round 11
// baseline (speedup 1.0000x reference)
#include <cuda_runtime.h>
#include <math.h>

#define B 32
#define N 1024
#define D 2048   // IMG_DIM
#define E 1024   // EMBED
#define CHUNKS 16
#define CROWS (N / CHUNKS)   // 64 rows per chunk
#define SUB 8                // rows per sub-chunk (reuse window = 64KB)

// ---------------- scratch (device globals; zero-initialized at module load).
// Invariant: g_v, g_outfeat, g_feats are ZERO on entry to kernel_launch
// (restored by k3/k7 at the end of each call).
__device__ float g_v[B * D];
__device__ float g_scores[B * N];
__device__ float g_part[B * CHUNKS * D];
__device__ float g_pm[B * CHUNKS];
__device__ float g_pl[B * CHUNKS];
__device__ float g_x[B * D];
__device__ float g_outfeat[B * E];
__device__ float g_feats[B * E];

// ================= K1: v[32,D] += cap[32,E] @ W1[E,D]  (NN tiled GEMM) ======
// Block: 64 d-columns x all 32 b x 128 e-slice. Grid (D/64=32, E/128=8)=256.
// Threads 256 = tx(8: 8 d each) x ty(8: 4 b each) x tz(4: 32 e each).
#define K1_KT 128
__global__ __launch_bounds__(256) void k1_gemm(const float* __restrict__ cap,
                                               const float* __restrict__ W1) {
    __shared__ float sA[32][K1_KT + 4];
    int m0 = blockIdx.x * 64;
    int k0 = blockIdx.y * K1_KT;
    int tid = threadIdx.x;
    int tx = tid & 7, ty = (tid >> 3) & 7, tz = tid >> 6;

    for (int i = tid; i < 32 * (K1_KT / 4); i += 256) {
        int b = i / (K1_KT / 4), kk = (i % (K1_KT / 4)) * 4;
        *(float4*)&sA[b][kk] = *(const float4*)&cap[b * E + k0 + kk];
    }
    __syncthreads();

    float acc[4][8];
#pragma unroll
    for (int i = 0; i < 4; i++)
#pragma unroll
        for (int j = 0; j < 8; j++) acc[i][j] = 0.f;

    int mbase = m0 + tx * 8;
#pragma unroll 4
    for (int k = tz * (K1_KT / 4); k < tz * (K1_KT / 4) + K1_KT / 4; k++) {
        float4 w0 = *(const float4*)&W1[(size_t)(k0 + k) * D + mbase];
        float4 w1 = *(const float4*)&W1[(size_t)(k0 + k) * D + mbase + 4];
#pragma unroll
        for (int i = 0; i < 4; i++) {
            float a = sA[ty * 4 + i][k];
            acc[i][0] += a * w0.x; acc[i][1] += a * w0.y;
            acc[i][2] += a * w0.z; acc[i][3] += a * w0.w;
            acc[i][4] += a * w1.x; acc[i][5] += a * w1.y;
            acc[i][6] += a * w1.z; acc[i][7] += a * w1.w;
        }
    }
#pragma unroll
    for (int i = 0; i < 4; i++) {
        int b = ty * 4 + i;
#pragma unroll
        for (int j = 0; j < 8; j++)
            atomicAdd(&g_v[(size_t)b * D + mbase + j], acc[i][j]);
    }
}

// ================= NT tiled GEMM body: out[32,E] += (A[32,K]+bias) @ W[E,K]^T
// Block: 64 m-rows of W x 32 b x KT k-slice. Threads as in k1_gemm.
// Inner 4-k iter: 8 LDG.128 (W) + 4 LDS.128 (A) + 128 FMA.
template <int KT>
__device__ __forceinline__ void gemm_nt_body(const float* __restrict__ A,
                                             const float* __restrict__ W,
                                             float* __restrict__ out, int K,
                                             const float* __restrict__ bias) {
    __shared__ float sA[32][KT + 4];
    int m0 = blockIdx.x * 64;
    int k0 = blockIdx.y * KT;
    int tid = threadIdx.x;
    int tx = tid & 7, ty = (tid >> 3) & 7, tz = tid >> 6;

    for (int i = tid; i < 32 * (KT / 4); i += 256) {
        int b = i / (KT / 4), kk = (i % (KT / 4)) * 4;
        float4 v = *(const float4*)&A[b * K + k0 + kk];
        if (bias) {
            float4 bv = *(const float4*)&bias[k0 + kk];
            v.x += bv.x; v.y += bv.y; v.z += bv.z; v.w += bv.w;
        }
        *(float4*)&sA[b][kk] = v;
    }
    __syncthreads();

    float acc[4][8];
#pragma unroll
    for (int i = 0; i < 4; i++)
#pragma unroll
        for (int j = 0; j < 8; j++) acc[i][j] = 0.f;

    int mbase = m0 + tx * 8;
    const float* Wb = W + (size_t)mbase * K + k0;
#pragma unroll 2
    for (int k = tz * (KT / 4); k < tz * (KT / 4) + KT / 4; k += 4) {
        float4 w[8];
#pragma unroll
        for (int j = 0; j < 8; j++) w[j] = *(const float4*)&Wb[(size_t)j * K + k];
        float4 a[4];
#pragma unroll
        for (int i = 0; i < 4; i++) a[i] = *(const float4*)&sA[ty * 4 + i][k];
#pragma unroll
        for (int i = 0; i < 4; i++)
#pragma unroll
            for (int j = 0; j < 8; j++)
                acc[i][j] += a[i].x * w[j].x + a[i].y * w[j].y
                           + a[i].z * w[j].z + a[i].w * w[j].w;
    }
#pragma unroll
    for (int i = 0; i < 4; i++) {
        int b = ty * 4 + i;
#pragma unroll
        for (int j = 0; j < 8; j++)
            atomicAdd(&out[b * E + mbase + j], acc[i][j]);
    }
}

// K5: g_outfeat += g_x @ ws1_w^T  (K=D, KT=256; grid (16,8))
__global__ __launch_bounds__(256) void k5_gemm(const float* __restrict__ W) {
    gemm_nt_body<256>(g_x, W, g_outfeat, D, nullptr);
}
// K6: g_feats += (g_outfeat + ws1_b) @ fc_w^T  (K=E, KT=128; grid (16,8))
__global__ __launch_bounds__(256) void k6_gemm(const float* __restrict__ W,
                                               const float* __restrict__ ws1_b) {
    gemm_nt_body<128>(g_outfeat, W, g_feats, E, ws1_b);
}

// ---------------- K2: fused scores + online softmax + pooling ---------------
// Sub-chunked so phase-2 re-reads hit L2 (window 8 rows = 64KB/block).
__global__ __launch_bounds__(256, 4) void k2_fused(const float* __restrict__ img,
                                                   const int* __restrict__ len) {
    __shared__ float sv[D];
    __shared__ float ssc[CROWS / SUB][SUB];

    int chunk = blockIdx.x, b = blockIdx.y;
    int L  = __ldg(&len[b]);
    int n0 = chunk * CROWS;
    int tid = threadIdx.x, warp = tid >> 5, lane = tid & 31;

    if (n0 >= L) {
        if (tid == 0) { g_pm[b * CHUNKS + chunk] = -INFINITY; g_pl[b * CHUNKS + chunk] = 0.f; }
        return;
    }
    int nv = min(CROWS, L - n0);

    for (int i = tid; i < D / 4; i += 256)
        ((float4*)sv)[i] = ((const float4*)g_v)[b * (D / 4) + i];
    __syncthreads();

    const float4* sv4  = (const float4*)sv;
    const float4* imgb = (const float4*)(img + ((size_t)b * N + n0) * D);
    int base = warp * 64 + lane;
    float4 a0 = make_float4(0.f, 0.f, 0.f, 0.f);
    float4 a1 = make_float4(0.f, 0.f, 0.f, 0.f);
    float m = -INFINITY, l = 0.f;

    for (int s = 0; s * SUB < nv; s++) {
        int rbase = s * SUB;
        int c = min(SUB, nv - rbase);
        if (warp < c) {
            const float4* row = imgb + (size_t)(rbase + warp) * (D / 4);
            float dot = 0.f;
#pragma unroll
            for (int j = 0; j < 16; j++) {
                float4 r = row[j * 32 + lane];
                float4 v = sv4[j * 32 + lane];
                dot += r.x * v.x + r.y * v.y + r.z * v.z + r.w * v.w;
            }
#pragma unroll
            for (int o = 16; o; o >>= 1) dot += __shfl_xor_sync(0xffffffffu, dot, o);
            if (lane == 0) {
                ssc[s][warp] = dot;
                g_scores[b * N + n0 + rbase + warp] = dot;
            }
        }
        __syncthreads();
        float sc_l = ((lane & 7) < c) ? ssc[s][lane & 7] : -INFINITY;
        float mnew = fmaxf(m, sc_l);
#pragma unroll
        for (int o = 4; o; o >>= 1) mnew = fmaxf(mnew, __shfl_xor_sync(0xffffffffu, mnew, o));
        float wexp = ((lane & 7) < c) ? __expf(sc_l - mnew) : 0.f;
        float lsub = wexp;
#pragma unroll
        for (int o = 4; o; o >>= 1) lsub += __shfl_xor_sync(0xffffffffu, lsub, o);
        if (mnew > m) {
            float scale = __expf(m - mnew);
            l *= scale;
            a0.x *= scale; a0.y *= scale; a0.z *= scale; a0.w *= scale;
            a1.x *= scale; a1.y *= scale; a1.z *= scale; a1.w *= scale;
            m = mnew;
        }
        l += lsub;
#pragma unroll
        for (int r = 0; r < SUB; r++) {
            if (r < c) {
                float wr = __shfl_sync(0xffffffffu, wexp, r);
                float4 r0 = imgb[(size_t)(rbase + r) * (D / 4) + base];
                float4 r1 = imgb[(size_t)(rbase + r) * (D / 4) + base + 32];
                a0.x += wr * r0.x; a0.y += wr * r0.y; a0.z += wr * r0.z; a0.w += wr * r0.w;
                a1.x += wr * r1.x; a1.y += wr * r1.y; a1.z += wr * r1.z; a1.w += wr * r1.w;
            }
        }
    }

    float4* part = (float4*)(g_part + (size_t)(b * CHUNKS + chunk) * D);
    part[base] = a0;
    part[base + 32] = a1;
    if (tid == 0) { g_pm[b * CHUNKS + chunk] = m; g_pl[b * CHUNKS + chunk] = l; }
}

// ---------------- K3: merge chunk partials -> g_x; attn weights; zero g_v ---
__global__ __launch_bounds__(256) void k3_merge(const int* __restrict__ len,
                                                float* __restrict__ attn_out) {
    __shared__ float sm_[CHUNKS], sl_[CHUNKS];
    __shared__ float4 sred[3][64];
    int b = blockIdx.x, ds = blockIdx.y, tid = threadIdx.x;
    int pos = tid & 63, cg = tid >> 6;
    if (tid < CHUNKS) { sm_[tid] = g_pm[b * CHUNKS + tid]; sl_[tid] = g_pl[b * CHUNKS + tid]; }
    __syncthreads();
    float M = -INFINITY;
#pragma unroll
    for (int c = 0; c < CHUNKS; c++) M = fmaxf(M, sm_[c]);
    float Lsum = 0.f;
#pragma unroll
    for (int c = 0; c < CHUNKS; c++)
        Lsum += __expf(sm_[c] - M) * sl_[c];
    float invL = 1.0f / Lsum;

    int i = ds * 64 + pos;
    float4 a = make_float4(0.f, 0.f, 0.f, 0.f);
#pragma unroll
    for (int k = 0; k < 4; k++) {
        int c = cg * 4 + k;
        float4 p = ((const float4*)g_part)[(size_t)(b * CHUNKS + c) * (D / 4) + i];
        float f = __expf(sm_[c] - M);
        a.x += f * p.x; a.y += f * p.y; a.z += f * p.z; a.w += f * p.w;
    }
    if (cg) sred[cg - 1][pos] = a;
    __syncthreads();
    if (cg == 0) {
        float4 r0 = sred[0][pos], r1 = sred[1][pos], r2 = sred[2][pos];
        a.x = (a.x + r0.x + r1.x + r2.x) * invL;
        a.y = (a.y + r0.y + r1.y + r2.y) * invL;
        a.z = (a.z + r0.z + r1.z + r2.z) * invL;
        a.w = (a.w + r0.w + r1.w + r2.w) * invL;
        ((float4*)g_x)[b * (D / 4) + i] = a;
    }
    g_v[b * D + ds * 256 + tid] = 0.0f;     // restore invariant
    if (ds == 0) {
        int Lb = __ldg(&len[b]);
        for (int n = tid; n < N; n += 256)
            attn_out[b * N + n] = (n < Lb) ? __expf(g_scores[b * N + n] - M) * invL : 0.f;
    }
}

// ---------------- K7: l2-normalize (g_feats + fc_b); restore invariants ------
__global__ __launch_bounds__(256) void k7_norm(const float* __restrict__ fc_b,
                                               float* __restrict__ out) {
    int b = blockIdx.x;
    __shared__ float red[8];
    int wid = threadIdx.x >> 5, lane = threadIdx.x & 31;
    float s = 0.f;
    for (int i = threadIdx.x; i < E; i += 256) {
        float v = g_feats[b * E + i] + fc_b[i];
        s += v * v;
    }
#pragma unroll
    for (int o = 16; o; o >>= 1) s += __shfl_xor_sync(0xffffffffu, s, o);
    if (lane == 0) red[wid] = s;
    __syncthreads();
    if (threadIdx.x == 0) {
        float t = 0.f;
#pragma unroll
        for (int i = 0; i < 8; i++) t += red[i];
        red[0] = 1.0f / sqrtf(t);
    }
    __syncthreads();
    float inv = red[0];
    for (int i = threadIdx.x; i < E; i += 256) {
        out[b * E + i] = (g_feats[b * E + i] + fc_b[i]) * inv;
        g_feats[b * E + i]   = 0.0f;     // restore invariants
        g_outfeat[b * E + i] = 0.0f;
    }
}

// ---------------- launch ------------------------------------------------------
extern "C" void kernel_launch(void* const* d_in, const int* in_sizes, int n_in,
                              void* d_out, int out_size) {
    const float* images = (const float*)d_in[0];  // [B,N,D]
    const float* cap    = (const float*)d_in[1];  // [B,E]
    const int*   len    = (const int*)  d_in[2];  // [B]
    const float* ws1_w  = (const float*)d_in[3];  // [E,D]
    const float* ws1_b  = (const float*)d_in[4];  // [E]
    const float* fc_w   = (const float*)d_in[5];  // [E,E]
    const float* fc_b   = (const float*)d_in[6];  // [E]
    float* out_features = (float*)d_out;          // [B,E]
    float* out_attn     = (float*)d_out + B * E;  // [B,N,1]

    k1_gemm<<<dim3(D / 64, E / K1_KT), 256>>>(cap, ws1_w);
    k2_fused<<<dim3(CHUNKS, B), 256>>>(images, len);
    k3_merge<<<dim3(B, 8), 256>>>(len, out_attn);
    k5_gemm<<<dim3(E / 64, D / 256), 256>>>(ws1_w);
    k6_gemm<<<dim3(E / 64, E / 128), 256>>>(fc_w, ws1_b);
    k7_norm<<<B, 256>>>(fc_b, out_features);
}

// round 12
// speedup vs baseline: 1.0018x; 1.0018x over previous
#include <cuda_runtime.h>
#include <math.h>

#define B 32
#define N 1024
#define D 2048   // IMG_DIM
#define E 1024   // EMBED
#define CHUNKS 16
#define CROWS (N / CHUNKS)   // 64 rows per chunk
#define SUB 8                // rows per sub-chunk (reuse window = 64KB)

// ---------------- scratch (device globals; zero-initialized at module load).
// Invariant: g_v, g_outfeat, g_feats are ZERO on entry to kernel_launch
// (restored by k3/k7 at the end of each call).
__device__ float g_v[B * D];
__device__ float g_scores[B * N];
__device__ float g_part[B * CHUNKS * D];
__device__ float g_pm[B * CHUNKS];
__device__ float g_pl[B * CHUNKS];
__device__ float g_x[B * D];
__device__ float g_outfeat[B * E];
__device__ float g_feats[B * E];

// ================= K1: v[32,D] += cap[32,E] @ W1[E,D]  (NN tiled GEMM) ======
// Block: 64 d-columns x all 32 b x 128 e-slice. Grid (D/64=32, E/128=8)=256.
// Threads 256 = tx(8: 8 d each) x ty(8: 4 b each) x tz(4: 32 e each).
#define K1_KT 128
__global__ __launch_bounds__(256) void k1_gemm(const float* __restrict__ cap,
                                               const float* __restrict__ W1) {
    __shared__ float sA[32][K1_KT + 4];
    int m0 = blockIdx.x * 64;
    int k0 = blockIdx.y * K1_KT;
    int tid = threadIdx.x;
    int tx = tid & 7, ty = (tid >> 3) & 7, tz = tid >> 6;

    for (int i = tid; i < 32 * (K1_KT / 4); i += 256) {
        int b = i / (K1_KT / 4), kk = (i % (K1_KT / 4)) * 4;
        *(float4*)&sA[b][kk] = *(const float4*)&cap[b * E + k0 + kk];
    }
    __syncthreads();

    float acc[4][8];
#pragma unroll
    for (int i = 0; i < 4; i++)
#pragma unroll
        for (int j = 0; j < 8; j++) acc[i][j] = 0.f;

    int mbase = m0 + tx * 8;
#pragma unroll 4
    for (int k = tz * (K1_KT / 4); k < tz * (K1_KT / 4) + K1_KT / 4; k++) {
        float4 w0 = *(const float4*)&W1[(size_t)(k0 + k) * D + mbase];
        float4 w1 = *(const float4*)&W1[(size_t)(k0 + k) * D + mbase + 4];
#pragma unroll
        for (int i = 0; i < 4; i++) {
            float a = sA[ty * 4 + i][k];
            acc[i][0] += a * w0.x; acc[i][1] += a * w0.y;
            acc[i][2] += a * w0.z; acc[i][3] += a * w0.w;
            acc[i][4] += a * w1.x; acc[i][5] += a * w1.y;
            acc[i][6] += a * w1.z; acc[i][7] += a * w1.w;
        }
    }
#pragma unroll
    for (int i = 0; i < 4; i++) {
        int b = ty * 4 + i;
#pragma unroll
        for (int j = 0; j < 8; j++)
            atomicAdd(&g_v[(size_t)b * D + mbase + j], acc[i][j]);
    }
}

// ================= NT tiled GEMM body: out[32,E] += (A[32,K]+bias) @ W[E,K]^T
// Block: 64 m-rows of W x 32 b x KT k-slice. Threads as in k1_gemm.
// Inner 4-k iter: 8 LDG.128 (W) + 4 LDS.128 (A) + 128 FMA.
template <int KT>
__device__ __forceinline__ void gemm_nt_body(const float* __restrict__ A,
                                             const float* __restrict__ W,
                                             float* __restrict__ out, int K,
                                             const float* __restrict__ bias) {
    __shared__ float sA[32][KT + 4];
    int m0 = blockIdx.x * 64;
    int k0 = blockIdx.y * KT;
    int tid = threadIdx.x;
    int tx = tid & 7, ty = (tid >> 3) & 7, tz = tid >> 6;

    for (int i = tid; i < 32 * (KT / 4); i += 256) {
        int b = i / (KT / 4), kk = (i % (KT / 4)) * 4;
        float4 v = *(const float4*)&A[b * K + k0 + kk];
        if (bias) {
            float4 bv = *(const float4*)&bias[k0 + kk];
            v.x += bv.x; v.y += bv.y; v.z += bv.z; v.w += bv.w;
        }
        *(float4*)&sA[b][kk] = v;
    }
    __syncthreads();

    float acc[4][8];
#pragma unroll
    for (int i = 0; i < 4; i++)
#pragma unroll
        for (int j = 0; j < 8; j++) acc[i][j] = 0.f;

    int mbase = m0 + tx * 8;
    const float* Wb = W + (size_t)mbase * K + k0;
#pragma unroll 2
    for (int k = tz * (KT / 4); k < tz * (KT / 4) + KT / 4; k += 4) {
        float4 w[8];
#pragma unroll
        for (int j = 0; j < 8; j++) w[j] = *(const float4*)&Wb[(size_t)j * K + k];
        float4 a[4];
#pragma unroll
        for (int i = 0; i < 4; i++) a[i] = *(const float4*)&sA[ty * 4 + i][k];
#pragma unroll
        for (int i = 0; i < 4; i++)
#pragma unroll
            for (int j = 0; j < 8; j++)
                acc[i][j] += a[i].x * w[j].x + a[i].y * w[j].y
                           + a[i].z * w[j].z + a[i].w * w[j].w;
    }
#pragma unroll
    for (int i = 0; i < 4; i++) {
        int b = ty * 4 + i;
#pragma unroll
        for (int j = 0; j < 8; j++)
            atomicAdd(&out[b * E + mbase + j], acc[i][j]);
    }
}

// K5: g_outfeat += g_x @ ws1_w^T  (K=D, KT=256; grid (16,8))
__global__ __launch_bounds__(256) void k5_gemm(const float* __restrict__ W) {
    gemm_nt_body<256>(g_x, W, g_outfeat, D, nullptr);
}
// K6: g_feats += (g_outfeat + ws1_b) @ fc_w^T  (K=E, KT=128; grid (16,8))
__global__ __launch_bounds__(256) void k6_gemm(const float* __restrict__ W,
                                               const float* __restrict__ ws1_b) {
    gemm_nt_body<128>(g_outfeat, W, g_feats, E, ws1_b);
}

// ---------------- K2: fused scores + online softmax + pooling ---------------
// Sub-chunked so phase-2 re-reads hit L2 (window 8 rows = 64KB/block).
__global__ __launch_bounds__(256, 4) void k2_fused(const float* __restrict__ img,
                                                   const int* __restrict__ len) {
    __shared__ float sv[D];
    __shared__ float ssc[CROWS / SUB][SUB];

    int chunk = blockIdx.x, b = blockIdx.y;
    int L  = __ldg(&len[b]);
    int n0 = chunk * CROWS;
    int tid = threadIdx.x, warp = tid >> 5, lane = tid & 31;

    if (n0 >= L) {
        if (tid == 0) { g_pm[b * CHUNKS + chunk] = -INFINITY; g_pl[b * CHUNKS + chunk] = 0.f; }
        return;
    }
    int nv = min(CROWS, L - n0);

    for (int i = tid; i < D / 4; i += 256)
        ((float4*)sv)[i] = ((const float4*)g_v)[b * (D / 4) + i];
    __syncthreads();

    const float4* sv4  = (const float4*)sv;
    const float4* imgb = (const float4*)(img + ((size_t)b * N + n0) * D);
    int base = warp * 64 + lane;
    float4 a0 = make_float4(0.f, 0.f, 0.f, 0.f);
    float4 a1 = make_float4(0.f, 0.f, 0.f, 0.f);
    float m = -INFINITY, l = 0.f;

    for (int s = 0; s * SUB < nv; s++) {
        int rbase = s * SUB;
        int c = min(SUB, nv - rbase);
        if (warp < c) {
            const float4* row = imgb + (size_t)(rbase + warp) * (D / 4);
            float dot = 0.f;
#pragma unroll
            for (int j = 0; j < 16; j++) {
                float4 r = row[j * 32 + lane];
                float4 v = sv4[j * 32 + lane];
                dot += r.x * v.x + r.y * v.y + r.z * v.z + r.w * v.w;
            }
#pragma unroll
            for (int o = 16; o; o >>= 1) dot += __shfl_xor_sync(0xffffffffu, dot, o);
            if (lane == 0) {
                ssc[s][warp] = dot;
                g_scores[b * N + n0 + rbase + warp] = dot;
            }
        }
        __syncthreads();
        float sc_l = ((lane & 7) < c) ? ssc[s][lane & 7] : -INFINITY;
        float mnew = fmaxf(m, sc_l);
#pragma unroll
        for (int o = 4; o; o >>= 1) mnew = fmaxf(mnew, __shfl_xor_sync(0xffffffffu, mnew, o));
        float wexp = ((lane & 7) < c) ? __expf(sc_l - mnew) : 0.f;
        float lsub = wexp;
#pragma unroll
        for (int o = 4; o; o >>= 1) lsub += __shfl_xor_sync(0xffffffffu, lsub, o);
        if (mnew > m) {
            float scale = __expf(m - mnew);
            l *= scale;
            a0.x *= scale; a0.y *= scale; a0.z *= scale; a0.w *= scale;
            a1.x *= scale; a1.y *= scale; a1.z *= scale; a1.w *= scale;
            m = mnew;
        }
        l += lsub;
#pragma unroll
        for (int r = 0; r < SUB; r++) {
            if (r < c) {
                float wr = __shfl_sync(0xffffffffu, wexp, r);
                float4 r0 = imgb[(size_t)(rbase + r) * (D / 4) + base];
                float4 r1 = imgb[(size_t)(rbase + r) * (D / 4) + base + 32];
                a0.x += wr * r0.x; a0.y += wr * r0.y; a0.z += wr * r0.z; a0.w += wr * r0.w;
                a1.x += wr * r1.x; a1.y += wr * r1.y; a1.z += wr * r1.z; a1.w += wr * r1.w;
            }
        }
    }

    float4* part = (float4*)(g_part + (size_t)(b * CHUNKS + chunk) * D);
    part[base] = a0;
    part[base + 32] = a1;
    if (tid == 0) { g_pm[b * CHUNKS + chunk] = m; g_pl[b * CHUNKS + chunk] = l; }
}

// ---------------- K3: merge chunk partials -> g_x; attn weights; zero g_v ---
__global__ __launch_bounds__(256) void k3_merge(const int* __restrict__ len,
                                                float* __restrict__ attn_out) {
    __shared__ float sm_[CHUNKS], sl_[CHUNKS];
    __shared__ float4 sred[3][64];
    int b = blockIdx.x, ds = blockIdx.y, tid = threadIdx.x;
    int pos = tid & 63, cg = tid >> 6;
    if (tid < CHUNKS) { sm_[tid] = g_pm[b * CHUNKS + tid]; sl_[tid] = g_pl[b * CHUNKS + tid]; }
    __syncthreads();
    float M = -INFINITY;
#pragma unroll
    for (int c = 0; c < CHUNKS; c++) M = fmaxf(M, sm_[c]);
    float Lsum = 0.f;
#pragma unroll
    for (int c = 0; c < CHUNKS; c++)
        Lsum += __expf(sm_[c] - M) * sl_[c];
    float invL = 1.0f / Lsum;

    int i = ds * 64 + pos;
    float4 a = make_float4(0.f, 0.f, 0.f, 0.f);
#pragma unroll
    for (int k = 0; k < 4; k++) {
        int c = cg * 4 + k;
        float4 p = ((const float4*)g_part)[(size_t)(b * CHUNKS + c) * (D / 4) + i];
        float f = __expf(sm_[c] - M);
        a.x += f * p.x; a.y += f * p.y; a.z += f * p.z; a.w += f * p.w;
    }
    if (cg) sred[cg - 1][pos] = a;
    __syncthreads();
    if (cg == 0) {
        float4 r0 = sred[0][pos], r1 = sred[1][pos], r2 = sred[2][pos];
        a.x = (a.x + r0.x + r1.x + r2.x) * invL;
        a.y = (a.y + r0.y + r1.y + r2.y) * invL;
        a.z = (a.z + r0.z + r1.z + r2.z) * invL;
        a.w = (a.w + r0.w + r1.w + r2.w) * invL;
        ((float4*)g_x)[b * (D / 4) + i] = a;
    }
    g_v[b * D + ds * 256 + tid] = 0.0f;     // restore invariant
    if (ds == 0) {
        int Lb = __ldg(&len[b]);
        for (int n = tid; n < N; n += 256)
            attn_out[b * N + n] = (n < Lb) ? __expf(g_scores[b * N + n] - M) * invL : 0.f;
    }
}

// ---------------- K7: l2-normalize (g_feats + fc_b); restore invariants ------
__global__ __launch_bounds__(256) void k7_norm(const float* __restrict__ fc_b,
                                               float* __restrict__ out) {
    int b = blockIdx.x;
    __shared__ float red[8];
    int wid = threadIdx.x >> 5, lane = threadIdx.x & 31;
    float s = 0.f;
    for (int i = threadIdx.x; i < E; i += 256) {
        float v = g_feats[b * E + i] + fc_b[i];
        s += v * v;
    }
#pragma unroll
    for (int o = 16; o; o >>= 1) s += __shfl_xor_sync(0xffffffffu, s, o);
    if (lane == 0) red[wid] = s;
    __syncthreads();
    if (threadIdx.x == 0) {
        float t = 0.f;
#pragma unroll
        for (int i = 0; i < 8; i++) t += red[i];
        red[0] = 1.0f / sqrtf(t);
    }
    __syncthreads();
    float inv = red[0];
    for (int i = threadIdx.x; i < E; i += 256) {
        out[b * E + i] = (g_feats[b * E + i] + fc_b[i]) * inv;
        g_feats[b * E + i]   = 0.0f;     // restore invariants
        g_outfeat[b * E + i] = 0.0f;
    }
}

// ---------------- launch ------------------------------------------------------
extern "C" void kernel_launch(void* const* d_in, const int* in_sizes, int n_in,
                              void* d_out, int out_size) {
    const float* images = (const float*)d_in[0];  // [B,N,D]
    const float* cap    = (const float*)d_in[1];  // [B,E]
    const int*   len    = (const int*)  d_in[2];  // [B]
    const float* ws1_w  = (const float*)d_in[3];  // [E,D]
    const float* ws1_b  = (const float*)d_in[4];  // [E]
    const float* fc_w   = (const float*)d_in[5];  // [E,E]
    const float* fc_b   = (const float*)d_in[6];  // [E]
    float* out_features = (float*)d_out;          // [B,E]
    float* out_attn     = (float*)d_out + B * E;  // [B,N,1]

    k1_gemm<<<dim3(D / 64, E / K1_KT), 256>>>(cap, ws1_w);
    k2_fused<<<dim3(CHUNKS, B), 256>>>(images, len);
    k3_merge<<<dim3(B, 8), 256>>>(len, out_attn);
    k5_gemm<<<dim3(E / 64, D / 256), 256>>>(ws1_w);
    k6_gemm<<<dim3(E / 64, E / 128), 256>>>(fc_w, ws1_b);
    k7_norm<<<B, 256>>>(fc_b, out_features);
}